// round 1
// baseline (speedup 1.0000x reference)
#include <cuda_runtime.h>
#include <cuda_bf16.h>
#include <math.h>
#include <stdint.h>

// Problem constants
#define D_MODEL 1024
#define N_HEADS 16
#define HEAD_DIM 64
#define BATCH 2
#define SEQ 2048
#define BS_TOT (BATCH * SEQ)          // 4096 rows
#define QKV_ELEMS (BATCH * N_HEADS * SEQ * HEAD_DIM)  // 4,194,304

// Scratch (device globals; no allocation allowed)
__device__ float g_q[QKV_ELEMS];
__device__ float g_k[QKV_ELEMS];
__device__ float g_v[QKV_ELEMS];
__device__ float g_ctx[BS_TOT * D_MODEL];
__device__ float g_cos_t[SEQ * 32];
__device__ float g_sin_t[SEQ * 32];

// ---------------------------------------------------------------------------
// RoPE table: cos/sin for (s, pair p) — fp64 for range reduction safety.
// token_positions may be int64 or int32 depending on JAX x64 config; sniff it.
// ---------------------------------------------------------------------------
__global__ void rope_table_kernel(const int* __restrict__ pos_raw) {
    int idx = blockIdx.x * blockDim.x + threadIdx.x;
    if (idx >= SEQ * 32) return;
    int s = idx >> 5;
    int p = idx & 31;
    // dtype sniff: int64 arange has zero high words at odd int32 slots
    bool is64 = (pos_raw[1] == 0 && pos_raw[3] == 0 && pos_raw[5] == 0);
    long long pos = is64 ? ((const long long*)pos_raw)[s] : (long long)pos_raw[s];
    // inv_freq = theta^{-2p/64} = exp(-p * ln(10000)/32)
    double inv = exp(-(double)p * 0.28782313662425572);  // ln(10000)/32
    double f = (double)pos * inv;
    g_cos_t[idx] = (float)cos(f);
    g_sin_t[idx] = (float)sin(f);
}

// ---------------------------------------------------------------------------
// NT SGEMM: C[m,n] = sum_k A[m,k] * B[n,k]   (A: 4096x1024 rm, B: 1024x1024 rm)
// 128x128 CTA tile, K-tile 16, 256 threads, 8x8 micro-tile.
// MODE 0: dst = g_q with RoPE     MODE 1: dst = g_k with RoPE
// MODE 2: dst = g_v (layout only) MODE 3: A = g_ctx, C = param (row-major out)
// ---------------------------------------------------------------------------
template <int MODE>
__global__ __launch_bounds__(256) void gemm_nt_k(const float* __restrict__ Ain,
                                                 const float* __restrict__ Bw,
                                                 float* __restrict__ Cout) {
    const int K = D_MODEL;
    const int N = D_MODEL;
    const float* A = (MODE == 3) ? g_ctx : Ain;

    __shared__ float As[16][132];
    __shared__ float Bs[16][132];

    int tid = threadIdx.x;
    int ty = tid >> 4;          // 0..15
    int tx = tid & 15;          // 0..15
    int m0 = blockIdx.y * 128;
    int n0b = blockIdx.x * 128;

    float acc[8][8];
#pragma unroll
    for (int i = 0; i < 8; i++)
#pragma unroll
        for (int j = 0; j < 8; j++) acc[i][j] = 0.0f;

    // loader mapping: 128 rows x 16 k; each thread: 2 float4 along K per operand
    int lr = tid >> 1;           // 0..127
    int lc = (tid & 1) * 8;      // 0 or 8
    const float* Aptr = A + (size_t)(m0 + lr) * K + lc;
    const float* Bptr = Bw + (size_t)(n0b + lr) * K + lc;

    for (int kt = 0; kt < K; kt += 16) {
        float4 a0 = *(const float4*)(Aptr + kt);
        float4 a1 = *(const float4*)(Aptr + kt + 4);
        float4 b0 = *(const float4*)(Bptr + kt);
        float4 b1 = *(const float4*)(Bptr + kt + 4);
        __syncthreads();   // previous compute done reading smem
        As[lc + 0][lr] = a0.x; As[lc + 1][lr] = a0.y;
        As[lc + 2][lr] = a0.z; As[lc + 3][lr] = a0.w;
        As[lc + 4][lr] = a1.x; As[lc + 5][lr] = a1.y;
        As[lc + 6][lr] = a1.z; As[lc + 7][lr] = a1.w;
        Bs[lc + 0][lr] = b0.x; Bs[lc + 1][lr] = b0.y;
        Bs[lc + 2][lr] = b0.z; Bs[lc + 3][lr] = b0.w;
        Bs[lc + 4][lr] = b1.x; Bs[lc + 5][lr] = b1.y;
        Bs[lc + 6][lr] = b1.z; Bs[lc + 7][lr] = b1.w;
        __syncthreads();
#pragma unroll
        for (int kk = 0; kk < 16; kk++) {
            float ra[8], rb[8];
            *(float4*)&ra[0] = *(const float4*)&As[kk][ty * 8];
            *(float4*)&ra[4] = *(const float4*)&As[kk][ty * 8 + 4];
            *(float4*)&rb[0] = *(const float4*)&Bs[kk][tx * 8];
            *(float4*)&rb[4] = *(const float4*)&Bs[kk][tx * 8 + 4];
#pragma unroll
            for (int i = 0; i < 8; i++)
#pragma unroll
                for (int j = 0; j < 8; j++) acc[i][j] += ra[i] * rb[j];
        }
    }

    if (MODE == 3) {
        // plain row-major output
        float* Cp = Cout + (size_t)(m0 + ty * 8) * N + n0b + tx * 8;
#pragma unroll
        for (int r = 0; r < 8; r++) {
            *(float4*)(Cp + (size_t)r * N)     = make_float4(acc[r][0], acc[r][1], acc[r][2], acc[r][3]);
            *(float4*)(Cp + (size_t)r * N + 4) = make_float4(acc[r][4], acc[r][5], acc[r][6], acc[r][7]);
        }
    } else {
        float* dst = (MODE == 0) ? g_q : (MODE == 1) ? g_k : g_v;
        int n0 = n0b + tx * 8;        // multiple of 8 -> stays within one head
        int h = n0 >> 6;
        int dd = n0 & 63;             // even
#pragma unroll
        for (int r = 0; r < 8; r++) {
            int m = m0 + ty * 8 + r;
            int b = m >> 11;          // /SEQ
            int s = m & (SEQ - 1);
            if (MODE != 2) {
                const float* ct = g_cos_t + s * 32;
                const float* st = g_sin_t + s * 32;
#pragma unroll
                for (int c = 0; c < 8; c += 2) {
                    int p = (dd + c) >> 1;
                    float cs = ct[p], sn = st[p];
                    float xe = acc[r][c], xo = acc[r][c + 1];
                    acc[r][c]     = xe * cs - xo * sn;
                    acc[r][c + 1] = xe * sn + xo * cs;
                }
            }
            float* o = dst + (((size_t)b * N_HEADS + h) * SEQ + s) * HEAD_DIM + dd;
            *(float4*)(o)     = make_float4(acc[r][0], acc[r][1], acc[r][2], acc[r][3]);
            *(float4*)(o + 4) = make_float4(acc[r][4], acc[r][5], acc[r][6], acc[r][7]);
        }
    }
}

// ---------------------------------------------------------------------------
// Flash attention, causal. One CTA = (64 queries) x (one b,h).
// 256 threads as 16x16, 4x4 micro-tile. KV tiles of 64, tiles above the
// diagonal skipped. smem: Qs[kd][m] 64x64, K/V shared buffer 64x64, Ps 64x64.
// Exactly 48 KB static smem.
// ---------------------------------------------------------------------------
__global__ __launch_bounds__(256) void flash_attn_kernel(float* __restrict__ ctx) {
    __shared__ float sm[12288];          // 49152 bytes
    float* Qs = sm;                      // [kd][m], stride 64
    float* KVs = sm + 4096;              // K: [kd][n] stride 64 ; V: [n][dd] stride 64
    float* Ps = sm + 8192;               // [m][n], stride 64

    int qb = blockIdx.x;                 // 0..31
    int bh = blockIdx.y;                 // 0..31 (b*16 + h)
    int tid = threadIdx.x;
    int ty = tid >> 4;                   // 0..15 -> rows ty*4..+3
    int tx = tid & 15;                   // 0..15 -> cols tx*4..+3

    const float* qbase = g_q + ((size_t)bh * SEQ + qb * 64) * HEAD_DIM;
    const float* kbase = g_k + (size_t)bh * SEQ * HEAD_DIM;
    const float* vbase = g_v + (size_t)bh * SEQ * HEAD_DIM;

    // loader mapping: row = tid/4 (0..63), colbase = (tid%4)*16
    int lrow = tid >> 2;
    int lcb = (tid & 3) << 4;

    // Load Q (scaled by 1/sqrt(d)=0.125), transposed into Qs[kd][m]
#pragma unroll
    for (int i = 0; i < 4; i++) {
        float4 t4 = *(const float4*)(qbase + (size_t)lrow * 64 + lcb + 4 * i);
        int c = lcb + 4 * i;
        Qs[(c + 0) * 64 + lrow] = t4.x * 0.125f;
        Qs[(c + 1) * 64 + lrow] = t4.y * 0.125f;
        Qs[(c + 2) * 64 + lrow] = t4.z * 0.125f;
        Qs[(c + 3) * 64 + lrow] = t4.w * 0.125f;
    }

    float mstate[4], lstate[4], o[4][4];
#pragma unroll
    for (int r = 0; r < 4; r++) {
        mstate[r] = -1e30f;
        lstate[r] = 0.0f;
#pragma unroll
        for (int c = 0; c < 4; c++) o[r][c] = 0.0f;
    }

    for (int kb = 0; kb <= qb; kb++) {
        __syncthreads();   // prev PV reads of KVs/Ps done; (first iter: nothing)
        // Load K tile transposed into KVs[kd][n]
        const float* kp = kbase + ((size_t)kb * 64 + lrow) * 64 + lcb;
#pragma unroll
        for (int i = 0; i < 4; i++) {
            float4 t4 = *(const float4*)(kp + 4 * i);
            int c = lcb + 4 * i;
            KVs[(c + 0) * 64 + lrow] = t4.x;
            KVs[(c + 1) * 64 + lrow] = t4.y;
            KVs[(c + 2) * 64 + lrow] = t4.z;
            KVs[(c + 3) * 64 + lrow] = t4.w;
        }
        __syncthreads();   // Qs (first iter) and Ks ready

        // scores: sreg[r][c] = sum_kd Q[m][kd]*K[n][kd]
        float sreg[4][4];
#pragma unroll
        for (int r = 0; r < 4; r++)
#pragma unroll
            for (int c = 0; c < 4; c++) sreg[r][c] = 0.0f;

#pragma unroll 8
        for (int kd = 0; kd < 64; kd++) {
            float qa[4], ka[4];
            *(float4*)qa = *(const float4*)&Qs[kd * 64 + ty * 4];
            *(float4*)ka = *(const float4*)&KVs[kd * 64 + tx * 4];
#pragma unroll
            for (int r = 0; r < 4; r++)
#pragma unroll
                for (int c = 0; c < 4; c++) sreg[r][c] += qa[r] * ka[c];
        }

        // causal mask (diagonal tile only)
        if (kb == qb) {
#pragma unroll
            for (int r = 0; r < 4; r++)
#pragma unroll
                for (int c = 0; c < 4; c++)
                    if (tx * 4 + c > ty * 4 + r) sreg[r][c] = -1e30f;
        }

        // online softmax per row (rows span 16 consecutive lanes -> shfl w16)
        float alpha[4];
#pragma unroll
        for (int r = 0; r < 4; r++) {
            float tm = fmaxf(fmaxf(sreg[r][0], sreg[r][1]), fmaxf(sreg[r][2], sreg[r][3]));
#pragma unroll
            for (int off = 8; off >= 1; off >>= 1)
                tm = fmaxf(tm, __shfl_xor_sync(0xffffffffu, tm, off, 16));
            float newm = fmaxf(mstate[r], tm);
            alpha[r] = __expf(mstate[r] - newm);
            mstate[r] = newm;
            float rs = 0.0f;
#pragma unroll
            for (int c = 0; c < 4; c++) {
                float p = __expf(sreg[r][c] - newm);
                sreg[r][c] = p;
                rs += p;
            }
#pragma unroll
            for (int off = 8; off >= 1; off >>= 1)
                rs += __shfl_xor_sync(0xffffffffu, rs, off, 16);
            lstate[r] = lstate[r] * alpha[r] + rs;
#pragma unroll
            for (int c = 0; c < 4; c++) o[r][c] *= alpha[r];
        }

        __syncthreads();   // all Ks reads done -> KVs reusable for V

        // store P tile [m][n]; load V naturally [n][dd]
#pragma unroll
        for (int r = 0; r < 4; r++)
            *(float4*)&Ps[(ty * 4 + r) * 64 + tx * 4] =
                make_float4(sreg[r][0], sreg[r][1], sreg[r][2], sreg[r][3]);

        const float* vp = vbase + ((size_t)kb * 64 + lrow) * 64 + lcb;
#pragma unroll
        for (int i = 0; i < 4; i++)
            *(float4*)&KVs[lrow * 64 + lcb + 4 * i] = *(const float4*)(vp + 4 * i);

        __syncthreads();   // Vs + Ps ready

        // O += P @ V
#pragma unroll 8
        for (int kn = 0; kn < 64; kn++) {
            float pv[4];
#pragma unroll
            for (int r = 0; r < 4; r++) pv[r] = Ps[(ty * 4 + r) * 64 + kn];
            float vv[4];
            *(float4*)vv = *(const float4*)&KVs[kn * 64 + tx * 4];
#pragma unroll
            for (int r = 0; r < 4; r++)
#pragma unroll
                for (int c = 0; c < 4; c++) o[r][c] += pv[r] * vv[c];
        }
    }

    // epilogue: normalize + write ctx (B*S, D) with head offset
    int b = bh >> 4;
    int h = bh & 15;
#pragma unroll
    for (int r = 0; r < 4; r++) {
        float inv = 1.0f / lstate[r];
        int s = qb * 64 + ty * 4 + r;
        float4 o4 = make_float4(o[r][0] * inv, o[r][1] * inv, o[r][2] * inv, o[r][3] * inv);
        *(float4*)&g_ctx[((size_t)b * SEQ + s) * D_MODEL + h * 64 + tx * 4] = o4;
    }
    (void)ctx;
}

// ---------------------------------------------------------------------------
extern "C" void kernel_launch(void* const* d_in, const int* in_sizes, int n_in,
                              void* d_out, int out_size) {
    const float* x  = (const float*)d_in[0];
    const float* wq = (const float*)d_in[1];
    const float* wk = (const float*)d_in[2];
    const float* wv = (const float*)d_in[3];
    const float* wo = (const float*)d_in[4];
    const int* pos  = (const int*)d_in[5];   // int32 or int64; sniffed in kernel
    float* out = (float*)d_out;

    rope_table_kernel<<<(SEQ * 32 + 255) / 256, 256>>>(pos);

    dim3 gg(D_MODEL / 128, BS_TOT / 128);    // (8, 32)
    gemm_nt_k<0><<<gg, 256>>>(x, wq, nullptr);   // Q + RoPE
    gemm_nt_k<1><<<gg, 256>>>(x, wk, nullptr);   // K + RoPE
    gemm_nt_k<2><<<gg, 256>>>(x, wv, nullptr);   // V

    dim3 fg(SEQ / 64, BATCH * N_HEADS);      // (32, 32)
    flash_attn_kernel<<<fg, 256>>>(nullptr);

    gemm_nt_k<3><<<gg, 256>>>(nullptr, wo, out); // out projection
}

// round 3
// speedup vs baseline: 2.0447x; 2.0447x over previous
#include <cuda_runtime.h>
#include <cuda_bf16.h>
#include <math.h>
#include <stdint.h>

// Problem constants
#define D_MODEL 1024
#define N_HEADS 16
#define HEAD_DIM 64
#define BATCH 2
#define SEQ 2048
#define BS_TOT (BATCH * SEQ)                           // 4096 rows
#define QKV_ELEMS (BATCH * N_HEADS * SEQ * HEAD_DIM)   // 4,194,304

// Scratch (device globals; no allocation allowed)
__device__ float g_q[QKV_ELEMS];
__device__ float g_k[QKV_ELEMS];
__device__ float g_v[QKV_ELEMS];
__device__ float g_ctx[BS_TOT * D_MODEL];
__device__ float g_cos_t[SEQ * 32];
__device__ float g_sin_t[SEQ * 32];

// ---------------------------------------------------------------------------
// helpers
// ---------------------------------------------------------------------------
__device__ __forceinline__ unsigned f2tf(float x) {
    unsigned r;
    asm("cvt.rna.tf32.f32 %0, %1;" : "=r"(r) : "f"(x));
    return r;
}

__device__ __forceinline__ void mma_tf32(float* c, unsigned a0, unsigned a1,
                                         unsigned a2, unsigned a3,
                                         unsigned b0, unsigned b1) {
    asm volatile(
        "mma.sync.aligned.m16n8k8.row.col.f32.tf32.tf32.f32 "
        "{%0,%1,%2,%3}, {%4,%5,%6,%7}, {%8,%9}, {%0,%1,%2,%3};\n"
        : "+f"(c[0]), "+f"(c[1]), "+f"(c[2]), "+f"(c[3])
        : "r"(a0), "r"(a1), "r"(a2), "r"(a3), "r"(b0), "r"(b1));
}

// exp(x) for x <= 0 (handles -1e30 -> 0), all on fma/alu pipes (no MUFU)
__device__ __forceinline__ float exp_fast(float x) {
    float y = x * 1.4426950408889634f;
    y = fmaxf(y, -126.0f);
    float tt = y + 12582912.0f;                  // 1.5 * 2^23 round-to-int trick
    int   n = __float_as_int(tt) - 0x4B400000;
    float f = y - (tt - 12582912.0f);            // f in [-0.5, 0.5]
    float p = 1.33978308e-3f;                    // ln2^5/120
    p = fmaf(p, f, 9.61812910e-3f);              // ln2^4/24
    p = fmaf(p, f, 5.55041087e-2f);              // ln2^3/6
    p = fmaf(p, f, 2.40226507e-1f);              // ln2^2/2
    p = fmaf(p, f, 6.93147181e-1f);              // ln2
    p = fmaf(p, f, 1.0f);
    return p * __int_as_float((n + 127) << 23);
}

// ---------------------------------------------------------------------------
// RoPE table (fp64 once). token_positions may be int64 or int32; sniff it.
// ---------------------------------------------------------------------------
__global__ void rope_table_kernel(const int* __restrict__ pos_raw) {
    int idx = blockIdx.x * blockDim.x + threadIdx.x;
    if (idx >= SEQ * 32) return;
    int s = idx >> 5;
    int p = idx & 31;
    bool is64 = (pos_raw[1] == 0 && pos_raw[3] == 0 && pos_raw[5] == 0);
    long long pos = is64 ? ((const long long*)pos_raw)[s] : (long long)pos_raw[s];
    double inv = exp(-(double)p * 0.28782313662425572);  // ln(10000)/32
    double f = (double)pos * inv;
    g_cos_t[idx] = (float)cos(f);
    g_sin_t[idx] = (float)sin(f);
}

// ---------------------------------------------------------------------------
// NT GEMM via tf32 mma.sync: C[m,n] = sum_k A[m,k]*B[n,k]
// CTA 128x128, kTile 16, 256 threads = 8 warps (2m x 4n), warp tile 64x32.
// MODE 0: g_q + RoPE   MODE 1: g_k + RoPE   MODE 2: g_v   MODE 3: g_ctx->Cout
// ---------------------------------------------------------------------------
template <int MODE>
__global__ __launch_bounds__(256) void gemm_tc(const float* __restrict__ Ain,
                                               const float* __restrict__ Bw,
                                               float* __restrict__ Cout) {
    const int K = D_MODEL;
    const float* A = (MODE == 3) ? g_ctx : Ain;

    __shared__ unsigned As[128 * 20];   // [row][k] stride 20 (conflict-free frags)
    __shared__ unsigned Bs[128 * 20];

    int tid = threadIdx.x;
    int warp = tid >> 5, lane = tid & 31;
    int g = lane >> 2, t = lane & 3;
    int wm = warp >> 2, wn = warp & 3;   // wm 0..1 (m), wn 0..3 (n)
    int m0 = blockIdx.y * 128;
    int n0 = blockIdx.x * 128;

    float acc[4][4][4];
#pragma unroll
    for (int i = 0; i < 4; i++)
#pragma unroll
        for (int j = 0; j < 4; j++)
#pragma unroll
            for (int r = 0; r < 4; r++) acc[i][j][r] = 0.0f;

    // loader: row = tid/2 (128 rows), k-offset = (tid&1)*8 (8 floats each)
    int lr = tid >> 1;
    int lc = (tid & 1) * 8;
    const float* Ap = A + (size_t)(m0 + lr) * K + lc;
    const float* Bp = Bw + (size_t)(n0 + lr) * K + lc;

    float4 ra0 = *(const float4*)(Ap);
    float4 ra1 = *(const float4*)(Ap + 4);
    float4 rb0 = *(const float4*)(Bp);
    float4 rb1 = *(const float4*)(Bp + 4);

    for (int kt = 0; kt < K; kt += 16) {
        __syncthreads();
        {
            uint4 u;
            u.x = f2tf(ra0.x); u.y = f2tf(ra0.y); u.z = f2tf(ra0.z); u.w = f2tf(ra0.w);
            *(uint4*)&As[lr * 20 + lc] = u;
            u.x = f2tf(ra1.x); u.y = f2tf(ra1.y); u.z = f2tf(ra1.z); u.w = f2tf(ra1.w);
            *(uint4*)&As[lr * 20 + lc + 4] = u;
            u.x = f2tf(rb0.x); u.y = f2tf(rb0.y); u.z = f2tf(rb0.z); u.w = f2tf(rb0.w);
            *(uint4*)&Bs[lr * 20 + lc] = u;
            u.x = f2tf(rb1.x); u.y = f2tf(rb1.y); u.z = f2tf(rb1.z); u.w = f2tf(rb1.w);
            *(uint4*)&Bs[lr * 20 + lc + 4] = u;
        }
        __syncthreads();
        if (kt + 16 < K) {   // prefetch next k-tile while computing this one
            ra0 = *(const float4*)(Ap + kt + 16);
            ra1 = *(const float4*)(Ap + kt + 20);
            rb0 = *(const float4*)(Bp + kt + 16);
            rb1 = *(const float4*)(Bp + kt + 20);
        }
#pragma unroll
        for (int ks = 0; ks < 16; ks += 8) {
            unsigned af[4][4];
#pragma unroll
            for (int mt = 0; mt < 4; mt++) {
                int row = wm * 64 + mt * 16;
                af[mt][0] = As[(row + g) * 20 + ks + t];
                af[mt][1] = As[(row + g + 8) * 20 + ks + t];
                af[mt][2] = As[(row + g) * 20 + ks + t + 4];
                af[mt][3] = As[(row + g + 8) * 20 + ks + t + 4];
            }
            unsigned bf[4][2];
#pragma unroll
            for (int nt = 0; nt < 4; nt++) {
                int col = wn * 32 + nt * 8;
                bf[nt][0] = Bs[(col + g) * 20 + ks + t];
                bf[nt][1] = Bs[(col + g) * 20 + ks + t + 4];
            }
#pragma unroll
            for (int mt = 0; mt < 4; mt++)
#pragma unroll
                for (int nt = 0; nt < 4; nt++)
                    mma_tf32(acc[mt][nt], af[mt][0], af[mt][1], af[mt][2], af[mt][3],
                             bf[nt][0], bf[nt][1]);
        }
    }

    // epilogue: C frag c0/c1 = cols (2t, 2t+1) = exactly a RoPE pair
    if (MODE == 3) {
#pragma unroll
        for (int mt = 0; mt < 4; mt++) {
            int m = m0 + wm * 64 + mt * 16 + g;
#pragma unroll
            for (int nt = 0; nt < 4; nt++) {
                int col = n0 + wn * 32 + nt * 8 + 2 * t;
                *(float2*)(Cout + (size_t)m * D_MODEL + col) =
                    make_float2(acc[mt][nt][0], acc[mt][nt][1]);
                *(float2*)(Cout + (size_t)(m + 8) * D_MODEL + col) =
                    make_float2(acc[mt][nt][2], acc[mt][nt][3]);
            }
        }
    } else {
        float* dst = (MODE == 0) ? g_q : (MODE == 1) ? g_k : g_v;
#pragma unroll
        for (int mt = 0; mt < 4; mt++) {
            int mA = m0 + wm * 64 + mt * 16 + g;
            int mB = mA + 8;
            int bA = mA >> 11, sA = mA & (SEQ - 1);
            int bB = mB >> 11, sB = mB & (SEQ - 1);
#pragma unroll
            for (int nt = 0; nt < 4; nt++) {
                int col = n0 + wn * 32 + nt * 8 + 2 * t;
                int h = col >> 6, dd = col & 63, p = dd >> 1;
                float x0 = acc[mt][nt][0], x1 = acc[mt][nt][1];
                float x2 = acc[mt][nt][2], x3 = acc[mt][nt][3];
                if (MODE != 2) {
                    float cA = g_cos_t[sA * 32 + p], nA = g_sin_t[sA * 32 + p];
                    float cB = g_cos_t[sB * 32 + p], nB = g_sin_t[sB * 32 + p];
                    float e0 = x0 * cA - x1 * nA, o0 = x0 * nA + x1 * cA;
                    float e1 = x2 * cB - x3 * nB, o1 = x2 * nB + x3 * cB;
                    x0 = e0; x1 = o0; x2 = e1; x3 = o1;
                }
                *(float2*)(dst + (((size_t)bA * N_HEADS + h) * SEQ + sA) * HEAD_DIM + dd) =
                    make_float2(x0, x1);
                *(float2*)(dst + (((size_t)bB * N_HEADS + h) * SEQ + sB) * HEAD_DIM + dd) =
                    make_float2(x2, x3);
            }
        }
    }
}

// ---------------------------------------------------------------------------
// Flash attention (causal) with tf32 mma. CTA = 64 queries x (b,h).
// 128 threads = 4 warps; warp w owns q rows [w*16, w*16+16).
// QK^T and PV both on tensor pipe; P routed C-frag -> A-frag via quad shuffles
// (never touches smem). exp on fma pipe.
// ---------------------------------------------------------------------------
__global__ __launch_bounds__(128) void flash_tc() {
    __shared__ unsigned Qs[64 * 68];   // Q [m][k], stride 68 -> conflict-free frags
    __shared__ unsigned KVs[64 * 72];  // K as [n][k] stride 68; V as [k][n] stride 72

    int qb = blockIdx.x;               // 0..31
    int bh = blockIdx.y;               // 0..31
    int tid = threadIdx.x;
    int warp = tid >> 5, lane = tid & 31;
    int g = lane >> 2, t = lane & 3;

    const float* qp = g_q + ((size_t)bh * SEQ + qb * 64) * HEAD_DIM;
    const float* kp0 = g_k + (size_t)bh * SEQ * HEAD_DIM;
    const float* vp0 = g_v + (size_t)bh * SEQ * HEAD_DIM;

    int lr = tid >> 1;                 // 0..63
    int lc = (tid & 1) * 32;

    // load Q (pre-scaled by 1/8), convert to tf32
    {
        const float* src = qp + (size_t)lr * 64 + lc;
        unsigned* dstp = Qs + lr * 68 + lc;
#pragma unroll
        for (int i = 0; i < 8; i++) {
            float4 v = *(const float4*)(src + 4 * i);
            uint4 u;
            u.x = f2tf(v.x * 0.125f); u.y = f2tf(v.y * 0.125f);
            u.z = f2tf(v.z * 0.125f); u.w = f2tf(v.w * 0.125f);
            *(uint4*)(dstp + 4 * i) = u;
        }
    }

    float oacc[8][4];
#pragma unroll
    for (int i = 0; i < 8; i++)
#pragma unroll
        for (int r = 0; r < 4; r++) oacc[i][r] = 0.0f;
    float mst0 = -1e30f, mst1 = -1e30f, lst0 = 0.0f, lst1 = 0.0f;

    for (int kb = 0; kb <= qb; kb++) {
        __syncthreads();   // prev PV done reading KVs
        {
            const float* src = kp0 + ((size_t)kb * 64 + lr) * 64 + lc;
            unsigned* dstp = KVs + lr * 68 + lc;
#pragma unroll
            for (int i = 0; i < 8; i++) {
                float4 v = *(const float4*)(src + 4 * i);
                uint4 u;
                u.x = f2tf(v.x); u.y = f2tf(v.y); u.z = f2tf(v.z); u.w = f2tf(v.w);
                *(uint4*)(dstp + 4 * i) = u;
            }
        }
        __syncthreads();   // K (and Q on first iter) visible

        // S = Q @ K^T  (warp: 16 x 64, 8 n-tiles, k = 64)
        float sacc[8][4];
#pragma unroll
        for (int i = 0; i < 8; i++)
#pragma unroll
            for (int r = 0; r < 4; r++) sacc[i][r] = 0.0f;

#pragma unroll
        for (int ks = 0; ks < 64; ks += 8) {
            int rowA = (warp * 16 + g) * 68;
            unsigned a0 = Qs[rowA + ks + t];
            unsigned a1 = Qs[rowA + 8 * 68 + ks + t];
            unsigned a2 = Qs[rowA + ks + t + 4];
            unsigned a3 = Qs[rowA + 8 * 68 + ks + t + 4];
#pragma unroll
            for (int nt = 0; nt < 8; nt++) {
                unsigned b0 = KVs[(nt * 8 + g) * 68 + ks + t];
                unsigned b1 = KVs[(nt * 8 + g) * 68 + ks + t + 4];
                mma_tf32(sacc[nt], a0, a1, a2, a3, b0, b1);
            }
        }

        // causal mask (diagonal tile only)
        if (kb == qb) {
            int rA = qb * 64 + warp * 16 + g;
            int rB = rA + 8;
#pragma unroll
            for (int nt = 0; nt < 8; nt++) {
                int c0 = kb * 64 + nt * 8 + 2 * t;
                if (c0 > rA) sacc[nt][0] = -1e30f;
                if (c0 + 1 > rA) sacc[nt][1] = -1e30f;
                if (c0 > rB) sacc[nt][2] = -1e30f;
                if (c0 + 1 > rB) sacc[nt][3] = -1e30f;
            }
        }

        // online softmax (rows rA = g, rB = g+8 of this warp's block)
        float mxA = -1e30f, mxB = -1e30f;
#pragma unroll
        for (int nt = 0; nt < 8; nt++) {
            mxA = fmaxf(mxA, fmaxf(sacc[nt][0], sacc[nt][1]));
            mxB = fmaxf(mxB, fmaxf(sacc[nt][2], sacc[nt][3]));
        }
        mxA = fmaxf(mxA, __shfl_xor_sync(0xffffffffu, mxA, 1));
        mxA = fmaxf(mxA, __shfl_xor_sync(0xffffffffu, mxA, 2));
        mxB = fmaxf(mxB, __shfl_xor_sync(0xffffffffu, mxB, 1));
        mxB = fmaxf(mxB, __shfl_xor_sync(0xffffffffu, mxB, 2));
        float nmA = fmaxf(mst0, mxA), nmB = fmaxf(mst1, mxB);
        float aA = exp_fast(mst0 - nmA), aB = exp_fast(mst1 - nmB);
        mst0 = nmA; mst1 = nmB;

        unsigned pf[8][4];
        float rsA = 0.0f, rsB = 0.0f;
#pragma unroll
        for (int nt = 0; nt < 8; nt++) {
            unsigned u0 = f2tf(exp_fast(sacc[nt][0] - nmA));
            unsigned u1 = f2tf(exp_fast(sacc[nt][1] - nmA));
            unsigned u2 = f2tf(exp_fast(sacc[nt][2] - nmB));
            unsigned u3 = f2tf(exp_fast(sacc[nt][3] - nmB));
            pf[nt][0] = u0; pf[nt][1] = u1; pf[nt][2] = u2; pf[nt][3] = u3;
            rsA += __uint_as_float(u0) + __uint_as_float(u1);
            rsB += __uint_as_float(u2) + __uint_as_float(u3);
        }
        rsA += __shfl_xor_sync(0xffffffffu, rsA, 1);
        rsA += __shfl_xor_sync(0xffffffffu, rsA, 2);
        rsB += __shfl_xor_sync(0xffffffffu, rsB, 1);
        rsB += __shfl_xor_sync(0xffffffffu, rsB, 2);
        lst0 = lst0 * aA + rsA;
        lst1 = lst1 * aB + rsB;
#pragma unroll
        for (int nt = 0; nt < 8; nt++) {
            oacc[nt][0] *= aA; oacc[nt][1] *= aA;
            oacc[nt][2] *= aB; oacc[nt][3] *= aB;
        }

        __syncthreads();   // QK done reading Ks
        {
            const float* src = vp0 + ((size_t)kb * 64 + lr) * 64 + lc;
            unsigned* dstp = KVs + lr * 72 + lc;
#pragma unroll
            for (int i = 0; i < 8; i++) {
                float4 v = *(const float4*)(src + 4 * i);
                uint4 u;
                u.x = f2tf(v.x); u.y = f2tf(v.y); u.z = f2tf(v.z); u.w = f2tf(v.w);
                *(uint4*)(dstp + 4 * i) = u;
            }
        }
        __syncthreads();   // V visible

        // O += P @ V ; P C-frags -> A-frags via quad shuffles
        int srcA = (lane & ~3) | (t >> 1);
        int srcB = srcA + 2;
        bool odd = (t & 1);
#pragma unroll
        for (int kt = 0; kt < 8; kt++) {
            unsigned v00 = __shfl_sync(0xffffffffu, pf[kt][0], srcA);
            unsigned v01 = __shfl_sync(0xffffffffu, pf[kt][1], srcA);
            unsigned v10 = __shfl_sync(0xffffffffu, pf[kt][2], srcA);
            unsigned v11 = __shfl_sync(0xffffffffu, pf[kt][3], srcA);
            unsigned w00 = __shfl_sync(0xffffffffu, pf[kt][0], srcB);
            unsigned w01 = __shfl_sync(0xffffffffu, pf[kt][1], srcB);
            unsigned w10 = __shfl_sync(0xffffffffu, pf[kt][2], srcB);
            unsigned w11 = __shfl_sync(0xffffffffu, pf[kt][3], srcB);
            unsigned a0 = odd ? v01 : v00;
            unsigned a1 = odd ? v11 : v10;
            unsigned a2 = odd ? w01 : w00;
            unsigned a3 = odd ? w11 : w10;
#pragma unroll
            for (int nt = 0; nt < 8; nt++) {
                unsigned b0 = KVs[(kt * 8 + t) * 72 + nt * 8 + g];
                unsigned b1 = KVs[(kt * 8 + t + 4) * 72 + nt * 8 + g];
                mma_tf32(oacc[nt], a0, a1, a2, a3, b0, b1);
            }
        }
    }

    // epilogue: normalize + write ctx (B*S, D)
    int b = bh >> 4, h = bh & 15;
    float iA = 1.0f / lst0, iB = 1.0f / lst1;
    int rowA = qb * 64 + warp * 16 + g;
    int rowB = rowA + 8;
#pragma unroll
    for (int nt = 0; nt < 8; nt++) {
        int col = h * 64 + nt * 8 + 2 * t;
        *(float2*)(g_ctx + ((size_t)b * SEQ + rowA) * D_MODEL + col) =
            make_float2(oacc[nt][0] * iA, oacc[nt][1] * iA);
        *(float2*)(g_ctx + ((size_t)b * SEQ + rowB) * D_MODEL + col) =
            make_float2(oacc[nt][2] * iB, oacc[nt][3] * iB);
    }
}

// ---------------------------------------------------------------------------
extern "C" void kernel_launch(void* const* d_in, const int* in_sizes, int n_in,
                              void* d_out, int out_size) {
    const float* x  = (const float*)d_in[0];
    const float* wq = (const float*)d_in[1];
    const float* wk = (const float*)d_in[2];
    const float* wv = (const float*)d_in[3];
    const float* wo = (const float*)d_in[4];
    const int* pos  = (const int*)d_in[5];
    float* out = (float*)d_out;

    rope_table_kernel<<<(SEQ * 32 + 255) / 256, 256>>>(pos);

    dim3 gg(D_MODEL / 128, BS_TOT / 128);     // (8, 32)
    gemm_tc<0><<<gg, 256>>>(x, wq, nullptr);  // Q + RoPE
    gemm_tc<1><<<gg, 256>>>(x, wk, nullptr);  // K + RoPE
    gemm_tc<2><<<gg, 256>>>(x, wv, nullptr);  // V

    dim3 fg(SEQ / 64, BATCH * N_HEADS);       // (32, 32)
    flash_tc<<<fg, 128>>>();

    gemm_tc<3><<<gg, 256>>>(nullptr, wo, out);  // out projection
}

// round 5
// speedup vs baseline: 2.4670x; 1.2065x over previous
#include <cuda_runtime.h>
#include <cuda_bf16.h>
#include <math.h>
#include <stdint.h>

#define D_MODEL 1024
#define N_HEADS 16
#define HEAD_DIM 64
#define BATCH 2
#define SEQ 2048
#define BS_TOT (BATCH * SEQ)
#define QKV_ELEMS (BATCH * N_HEADS * SEQ * HEAD_DIM)

__device__ float g_q[QKV_ELEMS];
__device__ float g_k[QKV_ELEMS];
__device__ float g_v[QKV_ELEMS];
__device__ float g_ctx[BS_TOT * D_MODEL];
__device__ float g_cos_t[SEQ * 32];
__device__ float g_sin_t[SEQ * 32];

// ---------------------------------------------------------------------------
__device__ __forceinline__ unsigned f2tf(float x) {
    unsigned r;
    asm("cvt.rna.tf32.f32 %0, %1;" : "=r"(r) : "f"(x));
    return r;
}

__device__ __forceinline__ void mma_tf32(float* c, unsigned a0, unsigned a1,
                                         unsigned a2, unsigned a3,
                                         unsigned b0, unsigned b1) {
    asm volatile(
        "mma.sync.aligned.m16n8k8.row.col.f32.tf32.tf32.f32 "
        "{%0,%1,%2,%3}, {%4,%5,%6,%7}, {%8,%9}, {%0,%1,%2,%3};\n"
        : "+f"(c[0]), "+f"(c[1]), "+f"(c[2]), "+f"(c[3])
        : "r"(a0), "r"(a1), "r"(a2), "r"(a3), "r"(b0), "r"(b1));
}

// exp(x) for x <= 0 on fma/alu pipes only (no MUFU)
__device__ __forceinline__ float exp_fast(float x) {
    float y = x * 1.4426950408889634f;
    y = fmaxf(y, -126.0f);
    float tt = y + 12582912.0f;
    int   n = __float_as_int(tt) - 0x4B400000;
    float f = y - (tt - 12582912.0f);
    float p = 1.33978308e-3f;
    p = fmaf(p, f, 9.61812910e-3f);
    p = fmaf(p, f, 5.55041087e-2f);
    p = fmaf(p, f, 2.40226507e-1f);
    p = fmaf(p, f, 6.93147181e-1f);
    p = fmaf(p, f, 1.0f);
    return p * __int_as_float((n + 127) << 23);
}

__device__ __forceinline__ void cpa16(uint32_t saddr, const void* gaddr) {
    asm volatile("cp.async.cg.shared.global [%0], [%1], 16;\n"
                 :: "r"(saddr), "l"(gaddr));
}
__device__ __forceinline__ void cpa_commit() {
    asm volatile("cp.async.commit_group;\n");
}
template <int N>
__device__ __forceinline__ void cpa_wait() {
    asm volatile("cp.async.wait_group %0;\n" :: "n"(N));
}

// ---------------------------------------------------------------------------
// RoPE table (fp64 once). token_positions may be int64 or int32; sniff it.
// ---------------------------------------------------------------------------
__global__ void rope_table_kernel(const int* __restrict__ pos_raw) {
    int idx = blockIdx.x * blockDim.x + threadIdx.x;
    if (idx >= SEQ * 32) return;
    int s = idx >> 5;
    int p = idx & 31;
    bool is64 = (pos_raw[1] == 0 && pos_raw[3] == 0 && pos_raw[5] == 0);
    long long pos = is64 ? ((const long long*)pos_raw)[s] : (long long)pos_raw[s];
    double inv = exp(-(double)p * 0.28782313662425572);
    double f = (double)pos * inv;
    g_cos_t[idx] = (float)cos(f);
    g_sin_t[idx] = (float)sin(f);
}

// ---------------------------------------------------------------------------
// NT GEMM via tf32 mma.sync, double-buffered smem (1 sync per k-tile).
// CTA 128x128, kTile 16, 256 threads = 8 warps (2m x 4n), warp tile 64x32.
// mode = mode_base + blockIdx.z:
//   0: g_q + RoPE   1: g_k + RoPE   2: g_v   3: A=g_ctx -> Cout
// ---------------------------------------------------------------------------
__global__ __launch_bounds__(256, 2) void gemm_all(const float* __restrict__ x,
                                                   const float* __restrict__ w0,
                                                   const float* __restrict__ w1,
                                                   const float* __restrict__ w2,
                                                   float* __restrict__ Cout,
                                                   int mode_base) {
    const int K = D_MODEL;
    int mode = mode_base + blockIdx.z;
    const float* A  = (mode == 3) ? g_ctx : x;
    const float* Bw = (mode == 1) ? w1 : (mode == 2) ? w2 : w0;

    __shared__ unsigned As[2][128 * 20];
    __shared__ unsigned Bs[2][128 * 20];

    int tid = threadIdx.x;
    int warp = tid >> 5, lane = tid & 31;
    int g = lane >> 2, t = lane & 3;
    int wm = warp >> 2, wn = warp & 3;
    int m0 = blockIdx.y * 128;
    int n0 = blockIdx.x * 128;

    float acc[4][4][4];
#pragma unroll
    for (int i = 0; i < 4; i++)
#pragma unroll
        for (int j = 0; j < 4; j++)
#pragma unroll
            for (int r = 0; r < 4; r++) acc[i][j][r] = 0.0f;

    int lr = tid >> 1;
    int lc = (tid & 1) * 8;
    const float* Ap = A + (size_t)(m0 + lr) * K + lc;
    const float* Bp = Bw + (size_t)(n0 + lr) * K + lc;

    // preload + store k-tile 0 into stage 0
    {
        float4 a0 = *(const float4*)(Ap);
        float4 a1 = *(const float4*)(Ap + 4);
        float4 b0 = *(const float4*)(Bp);
        float4 b1 = *(const float4*)(Bp + 4);
        uint4 u;
        u.x = f2tf(a0.x); u.y = f2tf(a0.y); u.z = f2tf(a0.z); u.w = f2tf(a0.w);
        *(uint4*)&As[0][lr * 20 + lc] = u;
        u.x = f2tf(a1.x); u.y = f2tf(a1.y); u.z = f2tf(a1.z); u.w = f2tf(a1.w);
        *(uint4*)&As[0][lr * 20 + lc + 4] = u;
        u.x = f2tf(b0.x); u.y = f2tf(b0.y); u.z = f2tf(b0.z); u.w = f2tf(b0.w);
        *(uint4*)&Bs[0][lr * 20 + lc] = u;
        u.x = f2tf(b1.x); u.y = f2tf(b1.y); u.z = f2tf(b1.z); u.w = f2tf(b1.w);
        *(uint4*)&Bs[0][lr * 20 + lc + 4] = u;
    }
    __syncthreads();

    int cur = 0;
    for (int kt = 0; kt < K; kt += 16) {
        bool hasNext = (kt + 16) < K;
        float4 na0, na1, nb0, nb1;
        if (hasNext) {
            na0 = *(const float4*)(Ap + kt + 16);
            na1 = *(const float4*)(Ap + kt + 20);
            nb0 = *(const float4*)(Bp + kt + 16);
            nb1 = *(const float4*)(Bp + kt + 20);
        }
#pragma unroll
        for (int ks = 0; ks < 16; ks += 8) {
            unsigned af[4][4];
#pragma unroll
            for (int mt = 0; mt < 4; mt++) {
                int row = wm * 64 + mt * 16;
                af[mt][0] = As[cur][(row + g) * 20 + ks + t];
                af[mt][1] = As[cur][(row + g + 8) * 20 + ks + t];
                af[mt][2] = As[cur][(row + g) * 20 + ks + t + 4];
                af[mt][3] = As[cur][(row + g + 8) * 20 + ks + t + 4];
            }
            unsigned bf[4][2];
#pragma unroll
            for (int nt = 0; nt < 4; nt++) {
                int col = wn * 32 + nt * 8;
                bf[nt][0] = Bs[cur][(col + g) * 20 + ks + t];
                bf[nt][1] = Bs[cur][(col + g) * 20 + ks + t + 4];
            }
#pragma unroll
            for (int mt = 0; mt < 4; mt++)
#pragma unroll
                for (int nt = 0; nt < 4; nt++)
                    mma_tf32(acc[mt][nt], af[mt][0], af[mt][1], af[mt][2], af[mt][3],
                             bf[nt][0], bf[nt][1]);
        }
        if (hasNext) {
            int nxt = cur ^ 1;
            uint4 u;
            u.x = f2tf(na0.x); u.y = f2tf(na0.y); u.z = f2tf(na0.z); u.w = f2tf(na0.w);
            *(uint4*)&As[nxt][lr * 20 + lc] = u;
            u.x = f2tf(na1.x); u.y = f2tf(na1.y); u.z = f2tf(na1.z); u.w = f2tf(na1.w);
            *(uint4*)&As[nxt][lr * 20 + lc + 4] = u;
            u.x = f2tf(nb0.x); u.y = f2tf(nb0.y); u.z = f2tf(nb0.z); u.w = f2tf(nb0.w);
            *(uint4*)&Bs[nxt][lr * 20 + lc] = u;
            u.x = f2tf(nb1.x); u.y = f2tf(nb1.y); u.z = f2tf(nb1.z); u.w = f2tf(nb1.w);
            *(uint4*)&Bs[nxt][lr * 20 + lc + 4] = u;
        }
        __syncthreads();
        cur ^= 1;
    }

    if (mode == 3) {
#pragma unroll
        for (int mt = 0; mt < 4; mt++) {
            int m = m0 + wm * 64 + mt * 16 + g;
#pragma unroll
            for (int nt = 0; nt < 4; nt++) {
                int col = n0 + wn * 32 + nt * 8 + 2 * t;
                *(float2*)(Cout + (size_t)m * D_MODEL + col) =
                    make_float2(acc[mt][nt][0], acc[mt][nt][1]);
                *(float2*)(Cout + (size_t)(m + 8) * D_MODEL + col) =
                    make_float2(acc[mt][nt][2], acc[mt][nt][3]);
            }
        }
    } else {
        float* dst = (mode == 0) ? g_q : (mode == 1) ? g_k : g_v;
        bool do_rope = (mode != 2);
#pragma unroll
        for (int mt = 0; mt < 4; mt++) {
            int mA = m0 + wm * 64 + mt * 16 + g;
            int mB = mA + 8;
            int bA = mA >> 11, sA = mA & (SEQ - 1);
            int bB = mB >> 11, sB = mB & (SEQ - 1);
#pragma unroll
            for (int nt = 0; nt < 4; nt++) {
                int col = n0 + wn * 32 + nt * 8 + 2 * t;
                int h = col >> 6, dd = col & 63, p = dd >> 1;
                float x0 = acc[mt][nt][0], x1 = acc[mt][nt][1];
                float x2 = acc[mt][nt][2], x3 = acc[mt][nt][3];
                if (do_rope) {
                    float cA = g_cos_t[sA * 32 + p], nA = g_sin_t[sA * 32 + p];
                    float cB = g_cos_t[sB * 32 + p], nB = g_sin_t[sB * 32 + p];
                    float e0 = x0 * cA - x1 * nA, o0 = x0 * nA + x1 * cA;
                    float e1 = x2 * cB - x3 * nB, o1 = x2 * nB + x3 * cB;
                    x0 = e0; x1 = o0; x2 = e1; x3 = o1;
                }
                *(float2*)(dst + (((size_t)bA * N_HEADS + h) * SEQ + sA) * HEAD_DIM + dd) =
                    make_float2(x0, x1);
                *(float2*)(dst + (((size_t)bB * N_HEADS + h) * SEQ + sB) * HEAD_DIM + dd) =
                    make_float2(x2, x3);
            }
        }
    }
}

// ---------------------------------------------------------------------------
// Flash attention (causal), tf32 mma.
// CTA = 128 queries x (b,h); 128 threads = 4 warps; warp w owns rows
// [w*32, w*32+32) as two m16 frags. Q persistent in registers.
// K and V staged fp32 via cp.async into separate smem buffers (tf32 cvt at
// use). KV tiles of 64; pipeline hides global latency.
// ---------------------------------------------------------------------------
__global__ __launch_bounds__(128) void flash_tc() {
    __shared__ float Ks[64 * 68];   // K [n][k], stride 68 (QK frag conflict-free)
    __shared__ float Vs[64 * 72];   // V [k][n], stride 72 (PV frag conflict-free)

    int qb = blockIdx.x;            // 0..15 (q-tile of 128 rows)
    int bh = blockIdx.y;            // 0..31
    int tid = threadIdx.x;
    int warp = tid >> 5, lane = tid & 31;
    int g = lane >> 2, t = lane & 3;

    const float* qp = g_q + ((size_t)bh * SEQ + qb * 128) * HEAD_DIM;
    const float* kp0 = g_k + (size_t)bh * SEQ * HEAD_DIM;
    const float* vp0 = g_v + (size_t)bh * SEQ * HEAD_DIM;

    uint32_t ksb = (uint32_t)__cvta_generic_to_shared(Ks);
    uint32_t vsb = (uint32_t)__cvta_generic_to_shared(Vs);

    // Q frags in registers (scaled by 1/8), 2 m-frags x 8 k-steps
    unsigned qf[2][8][4];
#pragma unroll
    for (int mf = 0; mf < 2; mf++) {
        int r0 = warp * 32 + mf * 16 + g;
#pragma unroll
        for (int ks = 0; ks < 8; ks++) {
            qf[mf][ks][0] = f2tf(qp[(size_t)r0 * 64 + ks * 8 + t] * 0.125f);
            qf[mf][ks][1] = f2tf(qp[(size_t)(r0 + 8) * 64 + ks * 8 + t] * 0.125f);
            qf[mf][ks][2] = f2tf(qp[(size_t)r0 * 64 + ks * 8 + t + 4] * 0.125f);
            qf[mf][ks][3] = f2tf(qp[(size_t)(r0 + 8) * 64 + ks * 8 + t + 4] * 0.125f);
        }
    }

    float oacc[2][8][4];
#pragma unroll
    for (int mf = 0; mf < 2; mf++)
#pragma unroll
        for (int i = 0; i < 8; i++)
#pragma unroll
            for (int r = 0; r < 4; r++) oacc[mf][i][r] = 0.0f;
    float mst[4], lst[4];
#pragma unroll
    for (int i = 0; i < 4; i++) { mst[i] = -1e30f; lst[i] = 0.0f; }

    int kbmax = 2 * qb + 1;

    // prologue: K(0) in flight
    {
        const float* kb_base = kp0;
#pragma unroll
        for (int i = 0; i < 8; i++) {
            int j = tid + 128 * i;
            int r = j >> 4, c = j & 15;
            cpa16(ksb + r * 272 + c * 16, kb_base + r * 64 + c * 4);
        }
        cpa_commit();
    }

    for (int kb = 0; kb <= kbmax; kb++) {
        __syncthreads();            // all prev PV reads of Vs done
        {                           // issue V(kb)
            const float* vb_base = vp0 + (size_t)kb * 64 * 64;
#pragma unroll
            for (int i = 0; i < 8; i++) {
                int j = tid + 128 * i;
                int r = j >> 4, c = j & 15;
                cpa16(vsb + r * 288 + c * 16, vb_base + r * 64 + c * 4);
            }
            cpa_commit();
        }
        cpa_wait<1>();              // my K(kb) chunks landed
        __syncthreads();            // everyone's K landed

        // S = Q @ K^T : 2 m-frags x 8 n-tiles, k = 64
        float sacc[2][8][4];
#pragma unroll
        for (int mf = 0; mf < 2; mf++)
#pragma unroll
            for (int i = 0; i < 8; i++)
#pragma unroll
                for (int r = 0; r < 4; r++) sacc[mf][i][r] = 0.0f;

#pragma unroll
        for (int ks = 0; ks < 8; ks++) {
#pragma unroll
            for (int nt = 0; nt < 8; nt++) {
                unsigned b0 = f2tf(Ks[(nt * 8 + g) * 68 + ks * 8 + t]);
                unsigned b1 = f2tf(Ks[(nt * 8 + g) * 68 + ks * 8 + t + 4]);
                mma_tf32(sacc[0][nt], qf[0][ks][0], qf[0][ks][1], qf[0][ks][2],
                         qf[0][ks][3], b0, b1);
                mma_tf32(sacc[1][nt], qf[1][ks][0], qf[1][ks][1], qf[1][ks][2],
                         qf[1][ks][3], b0, b1);
            }
        }

        // causal mask on diagonal-region tiles
        if (kb >= 2 * qb) {
#pragma unroll
            for (int mf = 0; mf < 2; mf++) {
                int rA = qb * 128 + warp * 32 + mf * 16 + g;
                int rB = rA + 8;
#pragma unroll
                for (int nt = 0; nt < 8; nt++) {
                    int c0 = kb * 64 + nt * 8 + 2 * t;
                    if (c0 > rA) sacc[mf][nt][0] = -1e30f;
                    if (c0 + 1 > rA) sacc[mf][nt][1] = -1e30f;
                    if (c0 > rB) sacc[mf][nt][2] = -1e30f;
                    if (c0 + 1 > rB) sacc[mf][nt][3] = -1e30f;
                }
            }
        }

        // online softmax; convert P to tf32 bits in place (sacc doubles as pf)
#pragma unroll
        for (int mf = 0; mf < 2; mf++) {
            float mxA = -1e30f, mxB = -1e30f;
#pragma unroll
            for (int nt = 0; nt < 8; nt++) {
                mxA = fmaxf(mxA, fmaxf(sacc[mf][nt][0], sacc[mf][nt][1]));
                mxB = fmaxf(mxB, fmaxf(sacc[mf][nt][2], sacc[mf][nt][3]));
            }
            mxA = fmaxf(mxA, __shfl_xor_sync(0xffffffffu, mxA, 1));
            mxA = fmaxf(mxA, __shfl_xor_sync(0xffffffffu, mxA, 2));
            mxB = fmaxf(mxB, __shfl_xor_sync(0xffffffffu, mxB, 1));
            mxB = fmaxf(mxB, __shfl_xor_sync(0xffffffffu, mxB, 2));
            float nmA = fmaxf(mst[mf * 2], mxA);
            float nmB = fmaxf(mst[mf * 2 + 1], mxB);
            float aA = exp_fast(mst[mf * 2] - nmA);
            float aB = exp_fast(mst[mf * 2 + 1] - nmB);
            mst[mf * 2] = nmA; mst[mf * 2 + 1] = nmB;

            float rsA = 0.0f, rsB = 0.0f;
#pragma unroll
            for (int nt = 0; nt < 8; nt++) {
                float p0 = exp_fast(sacc[mf][nt][0] - nmA);
                float p1 = exp_fast(sacc[mf][nt][1] - nmA);
                float p2 = exp_fast(sacc[mf][nt][2] - nmB);
                float p3 = exp_fast(sacc[mf][nt][3] - nmB);
                rsA += p0 + p1;
                rsB += p2 + p3;
                sacc[mf][nt][0] = __uint_as_float(f2tf(p0));
                sacc[mf][nt][1] = __uint_as_float(f2tf(p1));
                sacc[mf][nt][2] = __uint_as_float(f2tf(p2));
                sacc[mf][nt][3] = __uint_as_float(f2tf(p3));
            }
            rsA += __shfl_xor_sync(0xffffffffu, rsA, 1);
            rsA += __shfl_xor_sync(0xffffffffu, rsA, 2);
            rsB += __shfl_xor_sync(0xffffffffu, rsB, 1);
            rsB += __shfl_xor_sync(0xffffffffu, rsB, 2);
            lst[mf * 2] = lst[mf * 2] * aA + rsA;
            lst[mf * 2 + 1] = lst[mf * 2 + 1] * aB + rsB;
#pragma unroll
            for (int nt = 0; nt < 8; nt++) {
                oacc[mf][nt][0] *= aA; oacc[mf][nt][1] *= aA;
                oacc[mf][nt][2] *= aB; oacc[mf][nt][3] *= aB;
            }
        }

        __syncthreads();            // all QK reads of Ks done
        if (kb < kbmax) {           // issue K(kb+1)
            const float* kb_base = kp0 + (size_t)(kb + 1) * 64 * 64;
#pragma unroll
            for (int i = 0; i < 8; i++) {
                int j = tid + 128 * i;
                int r = j >> 4, c = j & 15;
                cpa16(ksb + r * 272 + c * 16, kb_base + r * 64 + c * 4);
            }
        }
        cpa_commit();               // (possibly-empty group keeps counts aligned)
        cpa_wait<1>();              // my V(kb) chunks landed
        __syncthreads();            // everyone's V landed

        // O += P @ V ; P C-frags -> A-frags via quad shuffles
        int srcA = (lane & ~3) | (t >> 1);
        int srcB = srcA + 2;
        bool odd = (t & 1);
#pragma unroll
        for (int kt = 0; kt < 8; kt++) {
            unsigned a[2][4];
#pragma unroll
            for (int mf = 0; mf < 2; mf++) {
                float v00 = __shfl_sync(0xffffffffu, sacc[mf][kt][0], srcA);
                float v01 = __shfl_sync(0xffffffffu, sacc[mf][kt][1], srcA);
                float v10 = __shfl_sync(0xffffffffu, sacc[mf][kt][2], srcA);
                float v11 = __shfl_sync(0xffffffffu, sacc[mf][kt][3], srcA);
                float w00 = __shfl_sync(0xffffffffu, sacc[mf][kt][0], srcB);
                float w01 = __shfl_sync(0xffffffffu, sacc[mf][kt][1], srcB);
                float w10 = __shfl_sync(0xffffffffu, sacc[mf][kt][2], srcB);
                float w11 = __shfl_sync(0xffffffffu, sacc[mf][kt][3], srcB);
                a[mf][0] = __float_as_uint(odd ? v01 : v00);
                a[mf][1] = __float_as_uint(odd ? v11 : v10);
                a[mf][2] = __float_as_uint(odd ? w01 : w00);
                a[mf][3] = __float_as_uint(odd ? w11 : w10);
            }
#pragma unroll
            for (int nt = 0; nt < 8; nt++) {
                unsigned b0 = f2tf(Vs[(kt * 8 + t) * 72 + nt * 8 + g]);
                unsigned b1 = f2tf(Vs[(kt * 8 + t + 4) * 72 + nt * 8 + g]);
                mma_tf32(oacc[0][nt], a[0][0], a[0][1], a[0][2], a[0][3], b0, b1);
                mma_tf32(oacc[1][nt], a[1][0], a[1][1], a[1][2], a[1][3], b0, b1);
            }
        }
    }

    // epilogue: normalize + write ctx (B*S, D)
    int b = bh >> 4, h = bh & 15;
#pragma unroll
    for (int mf = 0; mf < 2; mf++) {
        float iA = 1.0f / lst[mf * 2];
        float iB = 1.0f / lst[mf * 2 + 1];
        int rowA = qb * 128 + warp * 32 + mf * 16 + g;
        int rowB = rowA + 8;
#pragma unroll
        for (int nt = 0; nt < 8; nt++) {
            int col = h * 64 + nt * 8 + 2 * t;
            *(float2*)(g_ctx + ((size_t)b * SEQ + rowA) * D_MODEL + col) =
                make_float2(oacc[mf][nt][0] * iA, oacc[mf][nt][1] * iA);
            *(float2*)(g_ctx + ((size_t)b * SEQ + rowB) * D_MODEL + col) =
                make_float2(oacc[mf][nt][2] * iB, oacc[mf][nt][3] * iB);
        }
    }
}

// ---------------------------------------------------------------------------
extern "C" void kernel_launch(void* const* d_in, const int* in_sizes, int n_in,
                              void* d_out, int out_size) {
    const float* x  = (const float*)d_in[0];
    const float* wq = (const float*)d_in[1];
    const float* wk = (const float*)d_in[2];
    const float* wv = (const float*)d_in[3];
    const float* wo = (const float*)d_in[4];
    const int* pos  = (const int*)d_in[5];
    float* out = (float*)d_out;

    rope_table_kernel<<<(SEQ * 32 + 255) / 256, 256>>>(pos);

    dim3 gq(D_MODEL / 128, BS_TOT / 128, 3);   // (8, 32, 3) fused QKV
    gemm_all<<<gq, 256>>>(x, wq, wk, wv, nullptr, 0);

    dim3 fg(SEQ / 128, BATCH * N_HEADS);       // (16, 32)
    flash_tc<<<fg, 128>>>();

    dim3 gg(D_MODEL / 128, BS_TOT / 128, 1);   // out projection
    gemm_all<<<gg, 256>>>(nullptr, wo, nullptr, nullptr, out, 3);
}